// round 15
// baseline (speedup 1.0000x reference)
#include <cuda_runtime.h>
#include <cuda_bf16.h>
#include <cstdint>
#include <math.h>

#define S_LEN 2048
#define DMODEL 1024
#define NHEADS 16
#define HDIM 64
#define RADIUS 256
#define NGLOB 4

__device__ float g_P[(size_t)5 * S_LEN * DMODEL];

#define KGVG_KSPLIT 32
__device__ float g_KVGp[KGVG_KSPLIT][2][NGLOB][DMODEL];

#define ACT_ELEMS (S_LEN * DMODEL)
#define W_ELEMS   (DMODEL * DMODEL)
// GEMM operand splits: [0:ACT) activations (x, later O), then 4 weights transposed [n][k]
__device__ __nv_bfloat16 g_Bh[(size_t)ACT_ELEMS + 4 * W_ELEMS];
__device__ __nv_bfloat16 g_Bl[(size_t)ACT_ELEMS + 4 * W_ELEMS];
// attention operand splits (post-rope): Q,K in [s][d]; V transposed [d][s]
__device__ __nv_bfloat16 g_Qbh[ACT_ELEMS], g_Qbl[ACT_ELEMS];
__device__ __nv_bfloat16 g_Kbh[ACT_ELEMS], g_Kbl[ACT_ELEMS];
__device__ __nv_bfloat16 g_Vth[ACT_ELEMS], g_Vtl[ACT_ELEMS];

struct P4 { const float* p[4]; };

__device__ __forceinline__ void mma_bf16(float* c, const unsigned* a, const unsigned* b) {
    asm volatile(
        "mma.sync.aligned.m16n8k16.row.col.f32.bf16.bf16.f32 "
        "{%0,%1,%2,%3}, {%4,%5,%6,%7}, {%8,%9}, {%0,%1,%2,%3};"
        : "+f"(c[0]), "+f"(c[1]), "+f"(c[2]), "+f"(c[3])
        : "r"(a[0]), "r"(a[1]), "r"(a[2]), "r"(a[3]), "r"(b[0]), "r"(b[1]));
}

#define LDSM4(r, addr) \
    asm volatile("ldmatrix.sync.aligned.m8n8.x4.shared.b16 {%0,%1,%2,%3}, [%4];" \
        : "=r"((r)[0]), "=r"((r)[1]), "=r"((r)[2]), "=r"((r)[3]) : "r"(addr))

__device__ __forceinline__ void cpa16(void* dst, const void* src) {
    unsigned s = (unsigned)__cvta_generic_to_shared(dst);
    asm volatile("cp.async.cg.shared.global [%0], [%1], 16;" :: "r"(s), "l"(src));
}

__device__ __forceinline__ unsigned pack_bf16(float a, float b) {
    __nv_bfloat162 t = __floats2bfloat162_rn(a, b);
    return *reinterpret_cast<unsigned*>(&t);
}

// ---------------------------------------------------------------------------
// fused prep kernel: split_x + split_wt(x4) + kgvg_part, demuxed on blockIdx.x
//   [0, 2048)        : x fp32 -> bf16 hi/lo
//   [2048, 6144)     : weights transpose-split (z = idx/1024)
//   [6144, 6272)     : kgvg partials
// ---------------------------------------------------------------------------
#define PREP_X_BLOCKS  2048
#define PREP_W_BLOCKS  4096
#define PREP_KG_BLOCKS 128
#define PREP_BLOCKS (PREP_X_BLOCKS + PREP_W_BLOCKS + PREP_KG_BLOCKS)

__global__ __launch_bounds__(256) void prep_kernel(const float* __restrict__ x,
                                                   P4 ws,
                                                   const float* __restrict__ Wkg,
                                                   const float* __restrict__ Wvg)
{
    __shared__ float t[32][33];
    const int bxid = blockIdx.x;

    if (bxid < PREP_X_BLOCKS) {
        // ---- split x ----
        int i = bxid * 256 + threadIdx.x;        // over ACT_ELEMS/4
        float4 v = ((const float4*)x)[i];
        float f[4] = {v.x, v.y, v.z, v.w};
        ushort4 hv, lv;
        unsigned short* hp = &hv.x;
        unsigned short* lp = &lv.x;
#pragma unroll
        for (int e = 0; e < 4; e++) {
            __nv_bfloat16 hb = __float2bfloat16(f[e]);
            hp[e] = *reinterpret_cast<unsigned short*>(&hb);
            __nv_bfloat16 lb = __float2bfloat16(f[e] - __bfloat162float(hb));
            lp[e] = *reinterpret_cast<unsigned short*>(&lb);
        }
        ((ushort4*)g_Bh)[i] = hv;
        ((ushort4*)g_Bl)[i] = lv;
    } else if (bxid < PREP_X_BLOCKS + PREP_W_BLOCKS) {
        // ---- transpose + split one 32x32 weight tile ----
        int idx = bxid - PREP_X_BLOCKS;
        int z = idx >> 10;
        int rem = idx & 1023;
        int n0 = (rem & 31) * 32, k0 = (rem >> 5) * 32;
        const float* W = ws.p[z];
        const int tx = threadIdx.x & 31, ty = threadIdx.x >> 5;

#pragma unroll
        for (int j = 0; j < 4; j++)
            t[ty + j * 8][tx] = W[(size_t)(k0 + ty + j * 8) * DMODEL + n0 + tx];
        __syncthreads();

        size_t base = (size_t)ACT_ELEMS + (size_t)z * W_ELEMS;
#pragma unroll
        for (int j = 0; j < 4; j++) {
            int n = n0 + ty + j * 8;
            int k = k0 + tx;
            float v = t[tx][ty + j * 8];
            __nv_bfloat16 hb = __float2bfloat16(v);
            size_t idx2 = base + (size_t)n * DMODEL + k;
            g_Bh[idx2] = hb;
            g_Bl[idx2] = __float2bfloat16(v - __bfloat162float(hb));
        }
    } else {
        // ---- kgvg partial: 4 col-blocks x 32 ksplits ----
        int idx = bxid - PREP_X_BLOCKS - PREP_W_BLOCKS;
        const int d = (idx & 3) * 256 + threadIdx.x;
        const int kz = idx >> 2;
        float* xs = &t[0][0];                    // reuse smem (4*32 floats)
        if (threadIdx.x < NGLOB * 32) {
            int tt = threadIdx.x >> 5, k = threadIdx.x & 31;
            xs[tt * 32 + k] = x[(size_t)tt * DMODEL + kz * 32 + k];
        }
        __syncthreads();

        float ak[NGLOB] = {0.f, 0.f, 0.f, 0.f};
        float av[NGLOB] = {0.f, 0.f, 0.f, 0.f};
#pragma unroll 4
        for (int kk = 0; kk < 32; kk++) {
            size_t row = (size_t)(kz * 32 + kk) * DMODEL + d;
            float wk = __ldg(Wkg + row);
            float wv = __ldg(Wvg + row);
#pragma unroll
            for (int tt = 0; tt < NGLOB; tt++) {
                ak[tt] = fmaf(xs[tt * 32 + kk], wk, ak[tt]);
                av[tt] = fmaf(xs[tt * 32 + kk], wv, av[tt]);
            }
        }
#pragma unroll
        for (int tt = 0; tt < NGLOB; tt++) {
            g_KVGp[kz][0][tt][d] = ak[tt];
            g_KVGp[kz][1][tt][d] = av[tt];
        }
    }
}

__global__ __launch_bounds__(256) void kgvg_reduce_kernel()
{
    int idx = blockIdx.x * 256 + threadIdx.x;
    int d = idx & (DMODEL - 1);
    int t = (idx >> 10) & 3;
    int m = idx >> 12;
    float s = 0.f;
#pragma unroll
    for (int kz = 0; kz < KGVG_KSPLIT; kz++) s += g_KVGp[kz][m][t][d];
    g_P[(size_t)(3 + m) * ACT_ELEMS + (size_t)t * DMODEL + d] = s;
}

// V[s][d] (g_P slot 2) -> Vt bf16 hi/lo [d][s]
__global__ __launch_bounds__(256) void vt_split_kernel()
{
    __shared__ float t[32][33];
    const int s0 = blockIdx.x * 32, d0 = blockIdx.y * 32;
    const int tx = threadIdx.x & 31, ty = threadIdx.x >> 5;

#pragma unroll
    for (int j = 0; j < 4; j++)
        t[ty + j * 8][tx] = g_P[(size_t)2 * ACT_ELEMS + (size_t)(s0 + ty + j * 8) * DMODEL + d0 + tx];
    __syncthreads();

#pragma unroll
    for (int j = 0; j < 4; j++) {
        int d = d0 + ty + j * 8;
        int s = s0 + tx;
        float v = t[tx][ty + j * 8];
        __nv_bfloat16 hb = __float2bfloat16(v);
        size_t idx = (size_t)d * S_LEN + s;
        g_Vth[idx] = hb;
        g_Vtl[idx] = __float2bfloat16(v - __bfloat162float(hb));
    }
}

// ---------------------------------------------------------------------------
// 3xBF16 GEMM (m16n8k16), ldmatrix fragments, GBK=32, safe 2-stage buffer,
// fused RoPE, optional fp32 / bf16-split epilogues, split-K support.
// ---------------------------------------------------------------------------
#define GBK 32
#define STR 20
#define TILE_WORDS (128 * STR)
#define TILE_BYTES (TILE_WORDS * 4)
#define NSTAGE 2
#define GEMM_SMEM_BYTES (NSTAGE * 4 * TILE_BYTES)   // 81920

__device__ __forceinline__ void gemm3_body(const __nv_bfloat16* __restrict__ Agh,
                                           const __nv_bfloat16* __restrict__ Agl,
                                           const __nv_bfloat16* __restrict__ Bgh,
                                           const __nv_bfloat16* __restrict__ Bgl,
                                           float* __restrict__ C,
                                           __nv_bfloat16* __restrict__ outBh,
                                           __nv_bfloat16* __restrict__ outBl,
                                           bool do_rope,
                                           const float* __restrict__ cos_t,
                                           const float* __restrict__ sin_t,
                                           const int* __restrict__ pos,
                                           int kbase, int kcnt)
{
    extern __shared__ unsigned sm[];
    unsigned* uAh = sm;
    unsigned* uAl = sm + NSTAGE * TILE_WORDS;
    unsigned* uBh = sm + 2 * NSTAGE * TILE_WORDS;
    unsigned* uBl = sm + 3 * NSTAGE * TILE_WORDS;

    const int tid = threadIdx.x;
    const int lane = tid & 31;
    const int warp = tid >> 5;
    const int wm = warp >> 1;
    const int wn = warp & 1;
    const int bx = blockIdx.x, by = blockIdx.y;

    float acc[2][8][4];
#pragma unroll
    for (int mt = 0; mt < 2; mt++)
#pragma unroll
        for (int nt = 0; nt < 8; nt++)
#pragma unroll
            for (int e = 0; e < 4; e++) acc[mt][nt][e] = 0.f;

    auto load_stage = [&](int st, int k0) {
        unsigned* ah = uAh + st * TILE_WORDS;
        unsigned* al = uAl + st * TILE_WORDS;
        unsigned* bh = uBh + st * TILE_WORDS;
        unsigned* bl = uBl + st * TILE_WORDS;
#pragma unroll
        for (int it = 0; it < 2; it++) {
            int idx = it * 256 + tid;
            int r = idx >> 2, ch = idx & 3;
            int so = r * STR + ch * 4;
            size_t ga = (size_t)(by * 128 + r) * DMODEL + k0 + ch * 8;
            size_t gb = (size_t)(bx * 128 + r) * DMODEL + k0 + ch * 8;
            cpa16(ah + so, Agh + ga);
            cpa16(al + so, Agl + ga);
            cpa16(bh + so, Bgh + gb);
            cpa16(bl + so, Bgl + gb);
        }
    };

    const unsigned uAhS = (unsigned)__cvta_generic_to_shared(uAh);
    const unsigned uAlS = (unsigned)__cvta_generic_to_shared(uAl);
    const unsigned uBhS = (unsigned)__cvta_generic_to_shared(uBh);
    const unsigned uBlS = (unsigned)__cvta_generic_to_shared(uBl);
    unsigned aRel[2], bRel[4];
#pragma unroll
    for (int mt = 0; mt < 2; mt++)
        aRel[mt] = (unsigned)(((wm * 32 + mt * 16 + (lane & 15)) * STR) * 4 +
                              ((lane & 16) ? 16 : 0));
#pragma unroll
    for (int ntp = 0; ntp < 4; ntp++)
        bRel[ntp] = (unsigned)(((wn * 64 + ntp * 16 + ((lane & 16) ? 8 : 0) + (lane & 7)) * STR) * 4 +
                               ((lane & 8) ? 16 : 0));

    load_stage(0, kbase);
    asm volatile("cp.async.commit_group;");

    const int NT = kcnt / GBK;
#pragma unroll 1
    for (int i = 0; i < NT; i++) {
        const int st = i & 1;
        asm volatile("cp.async.wait_group 0;");
        __syncthreads();
        if (i + 1 < NT) load_stage(st ^ 1, kbase + (i + 1) * GBK);
        asm volatile("cp.async.commit_group;");

        const unsigned stB = (unsigned)(st * TILE_BYTES);

#pragma unroll
        for (int ks = 0; ks < 2; ks++) {
            const unsigned ko = (unsigned)(ks * 32);
            unsigned ah[2][4], al[2][4];
#pragma unroll
            for (int mt = 0; mt < 2; mt++) {
                LDSM4(ah[mt], uAhS + stB + aRel[mt] + ko);
                LDSM4(al[mt], uAlS + stB + aRel[mt] + ko);
            }
            unsigned bh4[4][4], bl4[4][4];
#pragma unroll
            for (int ntp = 0; ntp < 4; ntp++) {
                LDSM4(bh4[ntp], uBhS + stB + bRel[ntp] + ko);
                LDSM4(bl4[ntp], uBlS + stB + bRel[ntp] + ko);
            }
#pragma unroll
            for (int ntp = 0; ntp < 4; ntp++) {
#pragma unroll
                for (int s = 0; s < 2; s++) {
                    int nt = 2 * ntp + s;
                    unsigned bhp[2] = {bh4[ntp][2 * s], bh4[ntp][2 * s + 1]};
                    unsigned blp[2] = {bl4[ntp][2 * s], bl4[ntp][2 * s + 1]};
#pragma unroll
                    for (int mt = 0; mt < 2; mt++) {
                        mma_bf16(acc[mt][nt], ah[mt], bhp);
                        mma_bf16(acc[mt][nt], ah[mt], blp);
                        mma_bf16(acc[mt][nt], al[mt], bhp);
                    }
                }
            }
        }
    }

    if (do_rope) {
#pragma unroll
        for (int mt = 0; mt < 2; mt++) {
            int r0 = by * 128 + wm * 32 + mt * 16 + (lane >> 2);
            int p0 = __ldg(pos + r0);
            int p1 = __ldg(pos + r0 + 8);
#pragma unroll
            for (int nt = 0; nt < 4; nt++) {
#pragma unroll
                for (int e = 0; e < 2; e++) {
                    int d = nt * 8 + 2 * (lane & 3) + e;
                    {
                        float c0 = __ldg(cos_t + p0 * HDIM + d);
                        float s0 = __ldg(sin_t + p0 * HDIM + d);
                        float c1 = __ldg(cos_t + p0 * HDIM + d + 32);
                        float s1 = __ldg(sin_t + p0 * HDIM + d + 32);
                        float x0 = acc[mt][nt][e];
                        float x1 = acc[mt][nt + 4][e];
                        acc[mt][nt][e]     = x0 * c0 - x1 * s0;
                        acc[mt][nt + 4][e] = x1 * c1 + x0 * s1;
                    }
                    {
                        float c0 = __ldg(cos_t + p1 * HDIM + d);
                        float s0 = __ldg(sin_t + p1 * HDIM + d);
                        float c1 = __ldg(cos_t + p1 * HDIM + d + 32);
                        float s1 = __ldg(sin_t + p1 * HDIM + d + 32);
                        float x0 = acc[mt][nt][e + 2];
                        float x1 = acc[mt][nt + 4][e + 2];
                        acc[mt][nt][e + 2]     = x0 * c0 - x1 * s0;
                        acc[mt][nt + 4][e + 2] = x1 * c1 + x0 * s1;
                    }
                }
            }
        }
    }

#pragma unroll
    for (int mt = 0; mt < 2; mt++) {
        int r0 = by * 128 + wm * 32 + mt * 16 + (lane >> 2);
#pragma unroll
        for (int nt = 0; nt < 8; nt++) {
            int cc = bx * 128 + wn * 64 + nt * 8 + ((lane & 3) << 1);
            size_t i0x = (size_t)r0 * DMODEL + cc;
            size_t i1x = (size_t)(r0 + 8) * DMODEL + cc;
            if (C) {
                *(float2*)(C + i0x) = make_float2(acc[mt][nt][0], acc[mt][nt][1]);
                *(float2*)(C + i1x) = make_float2(acc[mt][nt][2], acc[mt][nt][3]);
            }
            if (outBh) {
                float v0 = acc[mt][nt][0], v1 = acc[mt][nt][1];
                float v2 = acc[mt][nt][2], v3 = acc[mt][nt][3];
                float h0 = __bfloat162float(__float2bfloat16(v0));
                float h1 = __bfloat162float(__float2bfloat16(v1));
                float h2 = __bfloat162float(__float2bfloat16(v2));
                float h3 = __bfloat162float(__float2bfloat16(v3));
                *(unsigned*)((__nv_bfloat16*)outBh + i0x) = pack_bf16(v0, v1);
                *(unsigned*)((__nv_bfloat16*)outBl + i0x) = pack_bf16(v0 - h0, v1 - h1);
                *(unsigned*)((__nv_bfloat16*)outBh + i1x) = pack_bf16(v2, v3);
                *(unsigned*)((__nv_bfloat16*)outBl + i1x) = pack_bf16(v2 - h2, v3 - h3);
            }
        }
    }
}

__global__ __launch_bounds__(256, 2) void proj_kernel(const float* __restrict__ cos_t,
                                                      const float* __restrict__ sin_t,
                                                      const int* __restrict__ pos)
{
    int z = blockIdx.z;   // 0=Q(rope) 1=K(rope) 2=V ; Q/K fp32 stores skipped
    float* C = (z == 2) ? g_P + (size_t)2 * ACT_ELEMS : nullptr;
    __nv_bfloat16* oh = (z == 0) ? g_Qbh : (z == 1) ? g_Kbh : nullptr;
    __nv_bfloat16* ol = (z == 0) ? g_Qbl : (z == 1) ? g_Kbl : nullptr;
    gemm3_body(g_Bh, g_Bl,
               g_Bh + ACT_ELEMS + (size_t)z * W_ELEMS,
               g_Bl + ACT_ELEMS + (size_t)z * W_ELEMS,
               C, oh, ol,
               z < 2, cos_t, sin_t, pos, 0, DMODEL);
}

// out GEMM split-K(2): partials into g_P slots 1 and 2 (dead by this point)
__global__ __launch_bounds__(256, 2) void out_gemm_part_kernel()
{
    int kz = blockIdx.z;
    gemm3_body(g_Bh, g_Bl,
               g_Bh + ACT_ELEMS + (size_t)3 * W_ELEMS,
               g_Bl + ACT_ELEMS + (size_t)3 * W_ELEMS,
               g_P + (size_t)(1 + kz) * ACT_ELEMS,
               nullptr, nullptr, false, nullptr, nullptr, nullptr,
               kz * (DMODEL / 2), DMODEL / 2);
}

__global__ __launch_bounds__(256) void out_reduce_kernel(float* __restrict__ out)
{
    int i = blockIdx.x * 256 + threadIdx.x;   // over ACT_ELEMS/4
    float4 a = ((const float4*)(g_P + ACT_ELEMS))[i];
    float4 b = ((const float4*)(g_P + 2 * (size_t)ACT_ELEMS))[i];
    ((float4*)out)[i] = make_float4(a.x + b.x, a.y + b.y, a.z + b.z, a.w + b.w);
}

// ---------------------------------------------------------------------------
// bf16x3 flash attention (round-10 winner; Q reconstructed from bf16 split)
// ---------------------------------------------------------------------------
#define ATS 36
#define CHUNK_WORDS (64 * ATS)
#define OFF_EXTRA (2 * 4 * CHUNK_WORDS)
#define ATT_SMEM_WORDS (OFF_EXTRA + HDIM + 2 * NGLOB * HDIM)

__global__ __launch_bounds__(128, 3) void attn_kernel()
{
    extern __shared__ unsigned smem_u[];
    float* Vg4 = (float*)(smem_u + OFF_EXTRA);
    float* KG4 = Vg4 + HDIM;
    float* VG4 = KG4 + NGLOB * HDIM;

    const int h  = blockIdx.x;
    const int i0 = blockIdx.y * 64;
    const int tid = threadIdx.x;
    const int lane = tid & 31;
    const int wq = tid >> 5;

    const float* V = g_P + (size_t)2 * ACT_ELEMS;

    if (tid < HDIM) {
        const float* vb = V + h * HDIM + tid;
        Vg4[tid] = vb[0] + vb[DMODEL] + vb[2 * DMODEL] + vb[3 * DMODEL];
    }
    for (int i2 = tid; i2 < 2 * NGLOB * HDIM; i2 += 128) {
        int mm = i2 >> 8;
        int t = (i2 >> 6) & 3;
        int c = i2 & 63;
        float val = g_P[(size_t)(3 + mm) * ACT_ELEMS + (size_t)t * DMODEL + h * HDIM + c];
        (mm ? VG4 : KG4)[t * HDIM + c] = val;
    }

    unsigned qh[4][4], ql[4][4];
    {
        const int r0 = i0 + wq * 16 + (lane >> 2);
        const int cb = h * HDIM + 2 * (lane & 3);
#pragma unroll
        for (int ks = 0; ks < 4; ks++) {
            size_t e00 = (size_t)r0 * DMODEL + cb + ks * 16;
            size_t e10 = (size_t)(r0 + 8) * DMODEL + cb + ks * 16;
            qh[ks][0] = *(const unsigned*)(g_Qbh + e00);
            qh[ks][1] = *(const unsigned*)(g_Qbh + e10);
            qh[ks][2] = *(const unsigned*)(g_Qbh + e00 + 8);
            qh[ks][3] = *(const unsigned*)(g_Qbh + e10 + 8);
            ql[ks][0] = *(const unsigned*)(g_Qbl + e00);
            ql[ks][1] = *(const unsigned*)(g_Qbl + e10);
            ql[ks][2] = *(const unsigned*)(g_Qbl + e00 + 8);
            ql[ks][3] = *(const unsigned*)(g_Qbl + e10 + 8);
        }
    }

    float out[8][4];
#pragma unroll
    for (int nt = 0; nt < 8; nt++)
#pragma unroll
        for (int e = 0; e < 4; e++) out[nt][e] = 0.f;
    float m0 = -3.4e38f, m1 = -3.4e38f, sum0 = 0.f, sum1 = 0.f;

    const int j_start = (i0 - RADIUS) > 0 ? (i0 - RADIUS) : 0;
    const int nchunks = (i0 + 64 - j_start) >> 6;

    auto load_chunk = [&](int st, int jc) {
        unsigned* base = smem_u + st * 4 * CHUNK_WORDS;
#pragma unroll
        for (int it = 0; it < 4; it++) {
            int idx = it * 128 + tid;
            int row = idx >> 3, ch = idx & 7;
            int so = row * ATS + ch * 4;
            size_t gk = (size_t)(jc + row) * DMODEL + h * HDIM + ch * 8;
            cpa16(base + so, g_Kbh + gk);
            cpa16(base + CHUNK_WORDS + so, g_Kbl + gk);
            size_t gv = (size_t)(h * HDIM + row) * S_LEN + jc + ch * 8;
            cpa16(base + 2 * CHUNK_WORDS + so, g_Vth + gv);
            cpa16(base + 3 * CHUNK_WORDS + so, g_Vtl + gv);
        }
    };

    const unsigned smemS = (unsigned)__cvta_generic_to_shared(smem_u);
    unsigned bRelA[4];
#pragma unroll
    for (int ntp = 0; ntp < 4; ntp++)
        bRelA[ntp] = (unsigned)(((ntp * 16 + ((lane & 16) ? 8 : 0) + (lane & 7)) * ATS) * 4 +
                                ((lane & 8) ? 16 : 0));

    load_chunk(0, j_start);
    asm volatile("cp.async.commit_group;");

#pragma unroll 1
    for (int ci = 0; ci < nchunks; ci++) {
        const int jc = j_start + ci * 64;
        const int st = ci & 1;
        __syncthreads();
        if (ci + 1 < nchunks) load_chunk(st ^ 1, jc + 64);
        asm volatile("cp.async.commit_group;");
        asm volatile("cp.async.wait_group 1;");
        __syncthreads();

        const unsigned KhS = smemS + (unsigned)(st * 4 * CHUNK_WORDS * 4);
        const unsigned KlS = KhS + CHUNK_WORDS * 4;
        const unsigned VhS = KhS + 2 * CHUNK_WORDS * 4;
        const unsigned VlS = KhS + 3 * CHUNK_WORDS * 4;

        float sc[8][4];
#pragma unroll
        for (int nt = 0; nt < 8; nt++)
#pragma unroll
            for (int e = 0; e < 4; e++) sc[nt][e] = 0.f;

#pragma unroll
        for (int ks = 0; ks < 4; ks++) {
#pragma unroll
            for (int ntp = 0; ntp < 4; ntp++) {
                unsigned kb[4], kbl[4];
                LDSM4(kb,  KhS + bRelA[ntp] + ks * 32);
                LDSM4(kbl, KlS + bRelA[ntp] + ks * 32);
#pragma unroll
                for (int s = 0; s < 2; s++) {
                    int nt = 2 * ntp + s;
                    unsigned bhp[2] = {kb[2 * s], kb[2 * s + 1]};
                    unsigned blp[2] = {kbl[2 * s], kbl[2 * s + 1]};
                    mma_bf16(sc[nt], qh[ks], bhp);
                    mma_bf16(sc[nt], qh[ks], blp);
                    mma_bf16(sc[nt], ql[ks], bhp);
                }
            }
        }

        const int c = lane & 3;
        const int ibase = i0 + wq * 16 + (lane >> 2);
        float mn0 = m0, mn1 = m1;
#pragma unroll
        for (int nt = 0; nt < 8; nt++) {
#pragma unroll
            for (int e = 0; e < 4; e++) {
                int i = ibase + ((e & 2) ? 8 : 0);
                int j = jc + nt * 8 + 2 * c + (e & 1);
                bool inw = (j <= i) && (i - j <= RADIUS);
                float raw = sc[nt][e] * 0.125f;
                float s;
                if (j < NGLOB) s = inw ? (raw + 1e9f) : 0.f;
                else           s = inw ? raw : -3.0e38f;
                sc[nt][e] = s;
                if (e & 2) mn1 = fmaxf(mn1, s); else mn0 = fmaxf(mn0, s);
            }
        }
#pragma unroll
        for (int o = 1; o < 4; o <<= 1) {
            mn0 = fmaxf(mn0, __shfl_xor_sync(0xffffffff, mn0, o));
            mn1 = fmaxf(mn1, __shfl_xor_sync(0xffffffff, mn1, o));
        }
        float esc0 = __expf(m0 - mn0);
        float esc1 = __expf(m1 - mn1);
        m0 = mn0; m1 = mn1;

        float ps0 = 0.f, ps1 = 0.f;
#pragma unroll
        for (int nt = 0; nt < 8; nt++) {
#pragma unroll
            for (int e = 0; e < 4; e++) {
                float p = __expf(sc[nt][e] - ((e & 2) ? m1 : m0));
                sc[nt][e] = p;
                if (e & 2) ps1 += p; else ps0 += p;
            }
        }
#pragma unroll
        for (int o = 1; o < 4; o <<= 1) {
            ps0 += __shfl_xor_sync(0xffffffff, ps0, o);
            ps1 += __shfl_xor_sync(0xffffffff, ps1, o);
        }
        sum0 = sum0 * esc0 + ps0;
        sum1 = sum1 * esc1 + ps1;
#pragma unroll
        for (int nt = 0; nt < 8; nt++) {
            out[nt][0] *= esc0; out[nt][1] *= esc0;
            out[nt][2] *= esc1; out[nt][3] *= esc1;
        }

#pragma unroll
        for (int ks2 = 0; ks2 < 4; ks2++) {
            float* s0v = sc[2 * ks2];
            float* s1v = sc[2 * ks2 + 1];
            float h00 = __bfloat162float(__float2bfloat16(s0v[0]));
            float h01 = __bfloat162float(__float2bfloat16(s0v[1]));
            float h02 = __bfloat162float(__float2bfloat16(s0v[2]));
            float h03 = __bfloat162float(__float2bfloat16(s0v[3]));
            float h10 = __bfloat162float(__float2bfloat16(s1v[0]));
            float h11 = __bfloat162float(__float2bfloat16(s1v[1]));
            float h12 = __bfloat162float(__float2bfloat16(s1v[2]));
            float h13 = __bfloat162float(__float2bfloat16(s1v[3]));
            unsigned ph[4], pl[4];
            ph[0] = pack_bf16(s0v[0], s0v[1]);
            ph[1] = pack_bf16(s0v[2], s0v[3]);
            ph[2] = pack_bf16(s1v[0], s1v[1]);
            ph[3] = pack_bf16(s1v[2], s1v[3]);
            pl[0] = pack_bf16(s0v[0] - h00, s0v[1] - h01);
            pl[1] = pack_bf16(s0v[2] - h02, s0v[3] - h03);
            pl[2] = pack_bf16(s1v[0] - h10, s1v[1] - h11);
            pl[3] = pack_bf16(s1v[2] - h12, s1v[3] - h13);
#pragma unroll
            for (int ntp = 0; ntp < 4; ntp++) {
                unsigned vb4[4], vbl4[4];
                LDSM4(vb4,  VhS + bRelA[ntp] + ks2 * 32);
                LDSM4(vbl4, VlS + bRelA[ntp] + ks2 * 32);
#pragma unroll
                for (int s = 0; s < 2; s++) {
                    int nt = 2 * ntp + s;
                    unsigned vbh[2] = {vb4[2 * s], vb4[2 * s + 1]};
                    unsigned vbl[2] = {vbl4[2 * s], vbl4[2 * s + 1]};
                    mma_bf16(out[nt], ph, vbh);
                    mma_bf16(out[nt], ph, vbl);
                    mma_bf16(out[nt], pl, vbh);
                }
            }
        }
    }

    if (j_start > 0) {
        float mn0 = fmaxf(m0, 0.f), mn1 = fmaxf(m1, 0.f);
        float esc0 = __expf(m0 - mn0), esc1 = __expf(m1 - mn1);
        float e0 = __expf(0.f - mn0), e1 = __expf(0.f - mn1);
        sum0 = sum0 * esc0 + 4.f * e0;
        sum1 = sum1 * esc1 + 4.f * e1;
#pragma unroll
        for (int nt = 0; nt < 8; nt++) {
            int col = nt * 8 + 2 * (lane & 3);
            out[nt][0] = out[nt][0] * esc0 + e0 * Vg4[col];
            out[nt][1] = out[nt][1] * esc0 + e0 * Vg4[col + 1];
            out[nt][2] = out[nt][2] * esc1 + e1 * Vg4[col];
            out[nt][3] = out[nt][3] * esc1 + e1 * Vg4[col + 1];
        }
    }

    float inv0 = 1.f / sum0, inv1 = 1.f / sum1;
    const int r0 = i0 + wq * 16 + (lane >> 2);

    // ---- fused global attention (q reconstructed = hi + lo) ----
    float w[2][4], deninv[2];
#pragma unroll
    for (int rr = 0; rr < 2; rr++) {
        int r = r0 + rr * 8;
        size_t qb = (size_t)r * DMODEL + h * HDIM;
        float dot[4] = {0.f, 0.f, 0.f, 0.f};
#pragma unroll
        for (int ks = 0; ks < 8; ks++) {
#pragma unroll
            for (int e2 = 0; e2 < 2; e2++) {
                int cc = ks * 8 + (lane & 3) + e2 * 4;
                float qv = __bfloat162float(g_Qbh[qb + cc]) +
                           __bfloat162float(g_Qbl[qb + cc]);
#pragma unroll
                for (int t = 0; t < 4; t++)
                    dot[t] = fmaf(qv, KG4[t * HDIM + cc], dot[t]);
            }
        }
#pragma unroll
        for (int t = 0; t < 4; t++) {
#pragma unroll
            for (int o = 1; o < 4; o <<= 1)
                dot[t] += __shfl_xor_sync(0xffffffff, dot[t], o);
            dot[t] *= 0.125f;
        }
        float mg = fmaxf(fmaxf(dot[0], dot[1]), fmaxf(dot[2], dot[3]));
        float den = 0.f;
#pragma unroll
        for (int t = 0; t < 4; t++) { w[rr][t] = __expf(dot[t] - mg); den += w[rr][t]; }
        deninv[rr] = 1.f / den;
    }

#pragma unroll
    for (int nt = 0; nt < 8; nt++) {
#pragma unroll
        for (int e = 0; e < 4; e++) {
            int rr = (e & 2) ? 1 : 0;
            int col = nt * 8 + 2 * (lane & 3) + (e & 1);
            float g = (w[rr][0] * VG4[0 * HDIM + col] + w[rr][1] * VG4[1 * HDIM + col] +
                       w[rr][2] * VG4[2 * HDIM + col] + w[rr][3] * VG4[3 * HDIM + col]) * deninv[rr];
            float v = out[nt][e] * (rr ? inv1 : inv0) + g;
            size_t idx = (size_t)(r0 + rr * 8) * DMODEL + h * HDIM + col;
            __nv_bfloat16 hb = __float2bfloat16(v);
            g_Bh[idx] = hb;
            g_Bl[idx] = __float2bfloat16(v - __bfloat162float(hb));
        }
    }
}

// ---------------------------------------------------------------------------
// launch
// ---------------------------------------------------------------------------
extern "C" void kernel_launch(void* const* d_in, const int* in_sizes, int n_in,
                              void* d_out, int out_size)
{
    const float* x     = (const float*)d_in[0];
    const float* cos_t = (const float*)d_in[1];
    const float* sin_t = (const float*)d_in[2];
    const int*   pos   = (const int*)d_in[3];
    P4 ws;
    ws.p[0] = (const float*)d_in[4];    // Wqs
    ws.p[1] = (const float*)d_in[5];    // Wks
    ws.p[2] = (const float*)d_in[6];    // Wvs
    ws.p[3] = (const float*)d_in[10];   // Wo
    const float* Wkg = (const float*)d_in[8];
    const float* Wvg = (const float*)d_in[9];
    float* out = (float*)d_out;

    static int attrs_set = 0;
    int attn_smem = ATT_SMEM_WORDS * 4;
    if (!attrs_set) {
        cudaFuncSetAttribute(attn_kernel,
                             cudaFuncAttributeMaxDynamicSharedMemorySize, attn_smem);
        cudaFuncSetAttribute(proj_kernel,
                             cudaFuncAttributeMaxDynamicSharedMemorySize, GEMM_SMEM_BYTES);
        cudaFuncSetAttribute(out_gemm_part_kernel,
                             cudaFuncAttributeMaxDynamicSharedMemorySize, GEMM_SMEM_BYTES);
        attrs_set = 1;
    }

    prep_kernel<<<PREP_BLOCKS, 256>>>(x, ws, Wkg, Wvg);
    kgvg_reduce_kernel<<<(2 * NGLOB * DMODEL) / 256, 256>>>();

    dim3 gp(DMODEL / 128, S_LEN / 128, 3);
    proj_kernel<<<gp, 256, GEMM_SMEM_BYTES>>>(cos_t, sin_t, pos);

    dim3 gvt(S_LEN / 32, DMODEL / 32);
    vt_split_kernel<<<gvt, 256>>>();

    dim3 ga(NHEADS, S_LEN / 64);
    attn_kernel<<<ga, 128, attn_smem>>>();

    dim3 go(DMODEL / 128, S_LEN / 128, 2);
    out_gemm_part_kernel<<<go, 256, GEMM_SMEM_BYTES>>>();
    out_reduce_kernel<<<(ACT_ELEMS / 4) / 256, 256>>>(out);
}

// round 16
// speedup vs baseline: 1.0145x; 1.0145x over previous
#include <cuda_runtime.h>
#include <cuda_bf16.h>
#include <cstdint>
#include <math.h>

#define S_LEN 2048
#define DMODEL 1024
#define NHEADS 16
#define HDIM 64
#define RADIUS 256
#define NGLOB 4

__device__ float g_P[(size_t)5 * S_LEN * DMODEL];

#define KGVG_KSPLIT 32
__device__ float g_KVGp[KGVG_KSPLIT][2][NGLOB][DMODEL];

#define ACT_ELEMS (S_LEN * DMODEL)
#define W_ELEMS   (DMODEL * DMODEL)
// GEMM operand splits: [0:ACT) activations (x, later O), then 4 weights transposed [n][k]
__device__ __nv_bfloat16 g_Bh[(size_t)ACT_ELEMS + 4 * W_ELEMS];
__device__ __nv_bfloat16 g_Bl[(size_t)ACT_ELEMS + 4 * W_ELEMS];
// attention operand splits (post-rope): Q,K,V all in [s][d]
__device__ __nv_bfloat16 g_Qbh[ACT_ELEMS], g_Qbl[ACT_ELEMS];
__device__ __nv_bfloat16 g_Kbh[ACT_ELEMS], g_Kbl[ACT_ELEMS];
__device__ __nv_bfloat16 g_Vbh[ACT_ELEMS], g_Vbl[ACT_ELEMS];

struct P4 { const float* p[4]; };

__device__ __forceinline__ void mma_bf16(float* c, const unsigned* a, const unsigned* b) {
    asm volatile(
        "mma.sync.aligned.m16n8k16.row.col.f32.bf16.bf16.f32 "
        "{%0,%1,%2,%3}, {%4,%5,%6,%7}, {%8,%9}, {%0,%1,%2,%3};"
        : "+f"(c[0]), "+f"(c[1]), "+f"(c[2]), "+f"(c[3])
        : "r"(a[0]), "r"(a[1]), "r"(a[2]), "r"(a[3]), "r"(b[0]), "r"(b[1]));
}

#define LDSM4(r, addr) \
    asm volatile("ldmatrix.sync.aligned.m8n8.x4.shared.b16 {%0,%1,%2,%3}, [%4];" \
        : "=r"((r)[0]), "=r"((r)[1]), "=r"((r)[2]), "=r"((r)[3]) : "r"(addr))

#define LDSM4T(r, addr) \
    asm volatile("ldmatrix.sync.aligned.m8n8.x4.trans.shared.b16 {%0,%1,%2,%3}, [%4];" \
        : "=r"((r)[0]), "=r"((r)[1]), "=r"((r)[2]), "=r"((r)[3]) : "r"(addr))

__device__ __forceinline__ void cpa16(void* dst, const void* src) {
    unsigned s = (unsigned)__cvta_generic_to_shared(dst);
    asm volatile("cp.async.cg.shared.global [%0], [%1], 16;" :: "r"(s), "l"(src));
}

__device__ __forceinline__ unsigned pack_bf16(float a, float b) {
    __nv_bfloat162 t = __floats2bfloat162_rn(a, b);
    return *reinterpret_cast<unsigned*>(&t);
}

// ---------------------------------------------------------------------------
// fused prep kernel: split_x + split_wt(x4) + kgvg_part, demuxed on blockIdx.x
// ---------------------------------------------------------------------------
#define PREP_X_BLOCKS  2048
#define PREP_W_BLOCKS  4096
#define PREP_KG_BLOCKS 128
#define PREP_BLOCKS (PREP_X_BLOCKS + PREP_W_BLOCKS + PREP_KG_BLOCKS)

__global__ __launch_bounds__(256) void prep_kernel(const float* __restrict__ x,
                                                   P4 ws,
                                                   const float* __restrict__ Wkg,
                                                   const float* __restrict__ Wvg)
{
    __shared__ float t[32][33];
    const int bxid = blockIdx.x;

    if (bxid < PREP_X_BLOCKS) {
        int i = bxid * 256 + threadIdx.x;
        float4 v = ((const float4*)x)[i];
        float f[4] = {v.x, v.y, v.z, v.w};
        ushort4 hv, lv;
        unsigned short* hp = &hv.x;
        unsigned short* lp = &lv.x;
#pragma unroll
        for (int e = 0; e < 4; e++) {
            __nv_bfloat16 hb = __float2bfloat16(f[e]);
            hp[e] = *reinterpret_cast<unsigned short*>(&hb);
            __nv_bfloat16 lb = __float2bfloat16(f[e] - __bfloat162float(hb));
            lp[e] = *reinterpret_cast<unsigned short*>(&lb);
        }
        ((ushort4*)g_Bh)[i] = hv;
        ((ushort4*)g_Bl)[i] = lv;
    } else if (bxid < PREP_X_BLOCKS + PREP_W_BLOCKS) {
        int idx = bxid - PREP_X_BLOCKS;
        int z = idx >> 10;
        int rem = idx & 1023;
        int n0 = (rem & 31) * 32, k0 = (rem >> 5) * 32;
        const float* W = ws.p[z];
        const int tx = threadIdx.x & 31, ty = threadIdx.x >> 5;

#pragma unroll
        for (int j = 0; j < 4; j++)
            t[ty + j * 8][tx] = W[(size_t)(k0 + ty + j * 8) * DMODEL + n0 + tx];
        __syncthreads();

        size_t base = (size_t)ACT_ELEMS + (size_t)z * W_ELEMS;
#pragma unroll
        for (int j = 0; j < 4; j++) {
            int n = n0 + ty + j * 8;
            int k = k0 + tx;
            float v = t[tx][ty + j * 8];
            __nv_bfloat16 hb = __float2bfloat16(v);
            size_t idx2 = base + (size_t)n * DMODEL + k;
            g_Bh[idx2] = hb;
            g_Bl[idx2] = __float2bfloat16(v - __bfloat162float(hb));
        }
    } else {
        int idx = bxid - PREP_X_BLOCKS - PREP_W_BLOCKS;
        const int d = (idx & 3) * 256 + threadIdx.x;
        const int kz = idx >> 2;
        float* xs = &t[0][0];
        if (threadIdx.x < NGLOB * 32) {
            int tt = threadIdx.x >> 5, k = threadIdx.x & 31;
            xs[tt * 32 + k] = x[(size_t)tt * DMODEL + kz * 32 + k];
        }
        __syncthreads();

        float ak[NGLOB] = {0.f, 0.f, 0.f, 0.f};
        float av[NGLOB] = {0.f, 0.f, 0.f, 0.f};
#pragma unroll 4
        for (int kk = 0; kk < 32; kk++) {
            size_t row = (size_t)(kz * 32 + kk) * DMODEL + d;
            float wk = __ldg(Wkg + row);
            float wv = __ldg(Wvg + row);
#pragma unroll
            for (int tt = 0; tt < NGLOB; tt++) {
                ak[tt] = fmaf(xs[tt * 32 + kk], wk, ak[tt]);
                av[tt] = fmaf(xs[tt * 32 + kk], wv, av[tt]);
            }
        }
#pragma unroll
        for (int tt = 0; tt < NGLOB; tt++) {
            g_KVGp[kz][0][tt][d] = ak[tt];
            g_KVGp[kz][1][tt][d] = av[tt];
        }
    }
}

__global__ __launch_bounds__(256) void kgvg_reduce_kernel()
{
    int idx = blockIdx.x * 256 + threadIdx.x;
    int d = idx & (DMODEL - 1);
    int t = (idx >> 10) & 3;
    int m = idx >> 12;
    float s = 0.f;
#pragma unroll
    for (int kz = 0; kz < KGVG_KSPLIT; kz++) s += g_KVGp[kz][m][t][d];
    g_P[(size_t)(3 + m) * ACT_ELEMS + (size_t)t * DMODEL + d] = s;
}

// ---------------------------------------------------------------------------
// 3xBF16 GEMM (m16n8k16), ldmatrix fragments, GBK=32, safe 2-stage buffer,
// fused RoPE, optional fp32 / bf16-split epilogues.
// ---------------------------------------------------------------------------
#define GBK 32
#define STR 20
#define TILE_WORDS (128 * STR)
#define TILE_BYTES (TILE_WORDS * 4)
#define NSTAGE 2
#define GEMM_SMEM_BYTES (NSTAGE * 4 * TILE_BYTES)   // 81920

__device__ __forceinline__ void gemm3_body(const __nv_bfloat16* __restrict__ Agh,
                                           const __nv_bfloat16* __restrict__ Agl,
                                           const __nv_bfloat16* __restrict__ Bgh,
                                           const __nv_bfloat16* __restrict__ Bgl,
                                           float* __restrict__ C,
                                           __nv_bfloat16* __restrict__ outBh,
                                           __nv_bfloat16* __restrict__ outBl,
                                           bool do_rope,
                                           const float* __restrict__ cos_t,
                                           const float* __restrict__ sin_t,
                                           const int* __restrict__ pos)
{
    extern __shared__ unsigned sm[];
    unsigned* uAh = sm;
    unsigned* uAl = sm + NSTAGE * TILE_WORDS;
    unsigned* uBh = sm + 2 * NSTAGE * TILE_WORDS;
    unsigned* uBl = sm + 3 * NSTAGE * TILE_WORDS;

    const int tid = threadIdx.x;
    const int lane = tid & 31;
    const int warp = tid >> 5;
    const int wm = warp >> 1;
    const int wn = warp & 1;
    const int bx = blockIdx.x, by = blockIdx.y;

    float acc[2][8][4];
#pragma unroll
    for (int mt = 0; mt < 2; mt++)
#pragma unroll
        for (int nt = 0; nt < 8; nt++)
#pragma unroll
            for (int e = 0; e < 4; e++) acc[mt][nt][e] = 0.f;

    auto load_stage = [&](int st, int k0) {
        unsigned* ah = uAh + st * TILE_WORDS;
        unsigned* al = uAl + st * TILE_WORDS;
        unsigned* bh = uBh + st * TILE_WORDS;
        unsigned* bl = uBl + st * TILE_WORDS;
#pragma unroll
        for (int it = 0; it < 2; it++) {
            int idx = it * 256 + tid;
            int r = idx >> 2, ch = idx & 3;
            int so = r * STR + ch * 4;
            size_t ga = (size_t)(by * 128 + r) * DMODEL + k0 + ch * 8;
            size_t gb = (size_t)(bx * 128 + r) * DMODEL + k0 + ch * 8;
            cpa16(ah + so, Agh + ga);
            cpa16(al + so, Agl + ga);
            cpa16(bh + so, Bgh + gb);
            cpa16(bl + so, Bgl + gb);
        }
    };

    const unsigned uAhS = (unsigned)__cvta_generic_to_shared(uAh);
    const unsigned uAlS = (unsigned)__cvta_generic_to_shared(uAl);
    const unsigned uBhS = (unsigned)__cvta_generic_to_shared(uBh);
    const unsigned uBlS = (unsigned)__cvta_generic_to_shared(uBl);
    unsigned aRel[2], bRel[4];
#pragma unroll
    for (int mt = 0; mt < 2; mt++)
        aRel[mt] = (unsigned)(((wm * 32 + mt * 16 + (lane & 15)) * STR) * 4 +
                              ((lane & 16) ? 16 : 0));
#pragma unroll
    for (int ntp = 0; ntp < 4; ntp++)
        bRel[ntp] = (unsigned)(((wn * 64 + ntp * 16 + ((lane & 16) ? 8 : 0) + (lane & 7)) * STR) * 4 +
                               ((lane & 8) ? 16 : 0));

    load_stage(0, 0);
    asm volatile("cp.async.commit_group;");

    const int NT = DMODEL / GBK;   // 32
#pragma unroll 1
    for (int i = 0; i < NT; i++) {
        const int st = i & 1;
        asm volatile("cp.async.wait_group 0;");
        __syncthreads();
        if (i + 1 < NT) load_stage(st ^ 1, (i + 1) * GBK);
        asm volatile("cp.async.commit_group;");

        const unsigned stB = (unsigned)(st * TILE_BYTES);

#pragma unroll
        for (int ks = 0; ks < 2; ks++) {
            const unsigned ko = (unsigned)(ks * 32);
            unsigned ah[2][4], al[2][4];
#pragma unroll
            for (int mt = 0; mt < 2; mt++) {
                LDSM4(ah[mt], uAhS + stB + aRel[mt] + ko);
                LDSM4(al[mt], uAlS + stB + aRel[mt] + ko);
            }
            unsigned bh4[4][4], bl4[4][4];
#pragma unroll
            for (int ntp = 0; ntp < 4; ntp++) {
                LDSM4(bh4[ntp], uBhS + stB + bRel[ntp] + ko);
                LDSM4(bl4[ntp], uBlS + stB + bRel[ntp] + ko);
            }
#pragma unroll
            for (int ntp = 0; ntp < 4; ntp++) {
#pragma unroll
                for (int s = 0; s < 2; s++) {
                    int nt = 2 * ntp + s;
                    unsigned bhp[2] = {bh4[ntp][2 * s], bh4[ntp][2 * s + 1]};
                    unsigned blp[2] = {bl4[ntp][2 * s], bl4[ntp][2 * s + 1]};
#pragma unroll
                    for (int mt = 0; mt < 2; mt++) {
                        mma_bf16(acc[mt][nt], ah[mt], bhp);
                        mma_bf16(acc[mt][nt], ah[mt], blp);
                        mma_bf16(acc[mt][nt], al[mt], bhp);
                    }
                }
            }
        }
    }

    if (do_rope) {
#pragma unroll
        for (int mt = 0; mt < 2; mt++) {
            int r0 = by * 128 + wm * 32 + mt * 16 + (lane >> 2);
            int p0 = __ldg(pos + r0);
            int p1 = __ldg(pos + r0 + 8);
#pragma unroll
            for (int nt = 0; nt < 4; nt++) {
#pragma unroll
                for (int e = 0; e < 2; e++) {
                    int d = nt * 8 + 2 * (lane & 3) + e;
                    {
                        float c0 = __ldg(cos_t + p0 * HDIM + d);
                        float s0 = __ldg(sin_t + p0 * HDIM + d);
                        float c1 = __ldg(cos_t + p0 * HDIM + d + 32);
                        float s1 = __ldg(sin_t + p0 * HDIM + d + 32);
                        float x0 = acc[mt][nt][e];
                        float x1 = acc[mt][nt + 4][e];
                        acc[mt][nt][e]     = x0 * c0 - x1 * s0;
                        acc[mt][nt + 4][e] = x1 * c1 + x0 * s1;
                    }
                    {
                        float c0 = __ldg(cos_t + p1 * HDIM + d);
                        float s0 = __ldg(sin_t + p1 * HDIM + d);
                        float c1 = __ldg(cos_t + p1 * HDIM + d + 32);
                        float s1 = __ldg(sin_t + p1 * HDIM + d + 32);
                        float x0 = acc[mt][nt][e + 2];
                        float x1 = acc[mt][nt + 4][e + 2];
                        acc[mt][nt][e + 2]     = x0 * c0 - x1 * s0;
                        acc[mt][nt + 4][e + 2] = x1 * c1 + x0 * s1;
                    }
                }
            }
        }
    }

#pragma unroll
    for (int mt = 0; mt < 2; mt++) {
        int r0 = by * 128 + wm * 32 + mt * 16 + (lane >> 2);
#pragma unroll
        for (int nt = 0; nt < 8; nt++) {
            int cc = bx * 128 + wn * 64 + nt * 8 + ((lane & 3) << 1);
            size_t i0x = (size_t)r0 * DMODEL + cc;
            size_t i1x = (size_t)(r0 + 8) * DMODEL + cc;
            if (C) {
                *(float2*)(C + i0x) = make_float2(acc[mt][nt][0], acc[mt][nt][1]);
                *(float2*)(C + i1x) = make_float2(acc[mt][nt][2], acc[mt][nt][3]);
            }
            if (outBh) {
                float v0 = acc[mt][nt][0], v1 = acc[mt][nt][1];
                float v2 = acc[mt][nt][2], v3 = acc[mt][nt][3];
                float h0 = __bfloat162float(__float2bfloat16(v0));
                float h1 = __bfloat162float(__float2bfloat16(v1));
                float h2 = __bfloat162float(__float2bfloat16(v2));
                float h3 = __bfloat162float(__float2bfloat16(v3));
                *(unsigned*)((__nv_bfloat16*)outBh + i0x) = pack_bf16(v0, v1);
                *(unsigned*)((__nv_bfloat16*)outBl + i0x) = pack_bf16(v0 - h0, v1 - h1);
                *(unsigned*)((__nv_bfloat16*)outBh + i1x) = pack_bf16(v2, v3);
                *(unsigned*)((__nv_bfloat16*)outBl + i1x) = pack_bf16(v2 - h2, v3 - h3);
            }
        }
    }
}

__global__ __launch_bounds__(256, 2) void proj_kernel(const float* __restrict__ cos_t,
                                                      const float* __restrict__ sin_t,
                                                      const int* __restrict__ pos)
{
    int z = blockIdx.z;   // 0=Q(rope) 1=K(rope) 2=V — all bf16-split only
    __nv_bfloat16* oh = (z == 0) ? g_Qbh : (z == 1) ? g_Kbh : g_Vbh;
    __nv_bfloat16* ol = (z == 0) ? g_Qbl : (z == 1) ? g_Kbl : g_Vbl;
    gemm3_body(g_Bh, g_Bl,
               g_Bh + ACT_ELEMS + (size_t)z * W_ELEMS,
               g_Bl + ACT_ELEMS + (size_t)z * W_ELEMS,
               nullptr, oh, ol,
               z < 2, cos_t, sin_t, pos);
}

__global__ __launch_bounds__(256, 2) void out_gemm_kernel(float* __restrict__ out)
{
    gemm3_body(g_Bh, g_Bl,
               g_Bh + ACT_ELEMS + (size_t)3 * W_ELEMS,
               g_Bl + ACT_ELEMS + (size_t)3 * W_ELEMS,
               out, nullptr, nullptr, false, nullptr, nullptr, nullptr);
}

// ---------------------------------------------------------------------------
// bf16x3 flash attention; V consumed from [s][d] via ldmatrix.trans.
// ---------------------------------------------------------------------------
#define ATS 36
#define CHUNK_WORDS (64 * ATS)
#define OFF_EXTRA (2 * 4 * CHUNK_WORDS)
#define ATT_SMEM_WORDS (OFF_EXTRA + HDIM + 2 * NGLOB * HDIM)

__global__ __launch_bounds__(128, 3) void attn_kernel()
{
    extern __shared__ unsigned smem_u[];
    float* Vg4 = (float*)(smem_u + OFF_EXTRA);
    float* KG4 = Vg4 + HDIM;
    float* VG4 = KG4 + NGLOB * HDIM;

    const int h  = blockIdx.x;
    const int i0 = blockIdx.y * 64;
    const int tid = threadIdx.x;
    const int lane = tid & 31;
    const int wq = tid >> 5;

    if (tid < HDIM) {
        float s = 0.f;
#pragma unroll
        for (int t = 0; t < NGLOB; t++) {
            size_t ix = (size_t)t * DMODEL + h * HDIM + tid;
            s += __bfloat162float(g_Vbh[ix]) + __bfloat162float(g_Vbl[ix]);
        }
        Vg4[tid] = s;
    }
    for (int i2 = tid; i2 < 2 * NGLOB * HDIM; i2 += 128) {
        int mm = i2 >> 8;
        int t = (i2 >> 6) & 3;
        int c = i2 & 63;
        float val = g_P[(size_t)(3 + mm) * ACT_ELEMS + (size_t)t * DMODEL + h * HDIM + c];
        (mm ? VG4 : KG4)[t * HDIM + c] = val;
    }

    unsigned qh[4][4], ql[4][4];
    {
        const int r0 = i0 + wq * 16 + (lane >> 2);
        const int cb = h * HDIM + 2 * (lane & 3);
#pragma unroll
        for (int ks = 0; ks < 4; ks++) {
            size_t e00 = (size_t)r0 * DMODEL + cb + ks * 16;
            size_t e10 = (size_t)(r0 + 8) * DMODEL + cb + ks * 16;
            qh[ks][0] = *(const unsigned*)(g_Qbh + e00);
            qh[ks][1] = *(const unsigned*)(g_Qbh + e10);
            qh[ks][2] = *(const unsigned*)(g_Qbh + e00 + 8);
            qh[ks][3] = *(const unsigned*)(g_Qbh + e10 + 8);
            ql[ks][0] = *(const unsigned*)(g_Qbl + e00);
            ql[ks][1] = *(const unsigned*)(g_Qbl + e10);
            ql[ks][2] = *(const unsigned*)(g_Qbl + e00 + 8);
            ql[ks][3] = *(const unsigned*)(g_Qbl + e10 + 8);
        }
    }

    float out[8][4];
#pragma unroll
    for (int nt = 0; nt < 8; nt++)
#pragma unroll
        for (int e = 0; e < 4; e++) out[nt][e] = 0.f;
    float m0 = -3.4e38f, m1 = -3.4e38f, sum0 = 0.f, sum1 = 0.f;

    const int j_start = (i0 - RADIUS) > 0 ? (i0 - RADIUS) : 0;
    const int nchunks = (i0 + 64 - j_start) >> 6;

    auto load_chunk = [&](int st, int jc) {
        unsigned* base = smem_u + st * 4 * CHUNK_WORDS;
#pragma unroll
        for (int it = 0; it < 4; it++) {
            int idx = it * 128 + tid;
            int row = idx >> 3, ch = idx & 7;
            int so = row * ATS + ch * 4;
            size_t g = (size_t)(jc + row) * DMODEL + h * HDIM + ch * 8;
            cpa16(base + so, g_Kbh + g);
            cpa16(base + CHUNK_WORDS + so, g_Kbl + g);
            cpa16(base + 2 * CHUNK_WORDS + so, g_Vbh + g);
            cpa16(base + 3 * CHUNK_WORDS + so, g_Vbl + g);
        }
    };

    const unsigned smemS = (unsigned)__cvta_generic_to_shared(smem_u);
    unsigned bRelA[4], vRelA[4];
#pragma unroll
    for (int ntp = 0; ntp < 4; ntp++) {
        bRelA[ntp] = (unsigned)(((ntp * 16 + ((lane & 16) ? 8 : 0) + (lane & 7)) * ATS) * 4 +
                                ((lane & 8) ? 16 : 0));
        // trans load: row = key (k), col bytes = d offset
        vRelA[ntp] = (unsigned)(((((lane & 8) ? 8 : 0) + (lane & 7)) * ATS) * 4 +
                                ntp * 32 + ((lane & 16) ? 16 : 0));
    }

    load_chunk(0, j_start);
    asm volatile("cp.async.commit_group;");

#pragma unroll 1
    for (int ci = 0; ci < nchunks; ci++) {
        const int jc = j_start + ci * 64;
        const int st = ci & 1;
        __syncthreads();
        if (ci + 1 < nchunks) load_chunk(st ^ 1, jc + 64);
        asm volatile("cp.async.commit_group;");
        asm volatile("cp.async.wait_group 1;");
        __syncthreads();

        const unsigned KhS = smemS + (unsigned)(st * 4 * CHUNK_WORDS * 4);
        const unsigned KlS = KhS + CHUNK_WORDS * 4;
        const unsigned VhS = KhS + 2 * CHUNK_WORDS * 4;
        const unsigned VlS = KhS + 3 * CHUNK_WORDS * 4;

        float sc[8][4];
#pragma unroll
        for (int nt = 0; nt < 8; nt++)
#pragma unroll
            for (int e = 0; e < 4; e++) sc[nt][e] = 0.f;

#pragma unroll
        for (int ks = 0; ks < 4; ks++) {
#pragma unroll
            for (int ntp = 0; ntp < 4; ntp++) {
                unsigned kb[4], kbl[4];
                LDSM4(kb,  KhS + bRelA[ntp] + ks * 32);
                LDSM4(kbl, KlS + bRelA[ntp] + ks * 32);
#pragma unroll
                for (int s = 0; s < 2; s++) {
                    int nt = 2 * ntp + s;
                    unsigned bhp[2] = {kb[2 * s], kb[2 * s + 1]};
                    unsigned blp[2] = {kbl[2 * s], kbl[2 * s + 1]};
                    mma_bf16(sc[nt], qh[ks], bhp);
                    mma_bf16(sc[nt], qh[ks], blp);
                    mma_bf16(sc[nt], ql[ks], bhp);
                }
            }
        }

        const int c = lane & 3;
        const int ibase = i0 + wq * 16 + (lane >> 2);
        float mn0 = m0, mn1 = m1;
#pragma unroll
        for (int nt = 0; nt < 8; nt++) {
#pragma unroll
            for (int e = 0; e < 4; e++) {
                int i = ibase + ((e & 2) ? 8 : 0);
                int j = jc + nt * 8 + 2 * c + (e & 1);
                bool inw = (j <= i) && (i - j <= RADIUS);
                float raw = sc[nt][e] * 0.125f;
                float s;
                if (j < NGLOB) s = inw ? (raw + 1e9f) : 0.f;
                else           s = inw ? raw : -3.0e38f;
                sc[nt][e] = s;
                if (e & 2) mn1 = fmaxf(mn1, s); else mn0 = fmaxf(mn0, s);
            }
        }
#pragma unroll
        for (int o = 1; o < 4; o <<= 1) {
            mn0 = fmaxf(mn0, __shfl_xor_sync(0xffffffff, mn0, o));
            mn1 = fmaxf(mn1, __shfl_xor_sync(0xffffffff, mn1, o));
        }
        float esc0 = __expf(m0 - mn0);
        float esc1 = __expf(m1 - mn1);
        m0 = mn0; m1 = mn1;

        float ps0 = 0.f, ps1 = 0.f;
#pragma unroll
        for (int nt = 0; nt < 8; nt++) {
#pragma unroll
            for (int e = 0; e < 4; e++) {
                float p = __expf(sc[nt][e] - ((e & 2) ? m1 : m0));
                sc[nt][e] = p;
                if (e & 2) ps1 += p; else ps0 += p;
            }
        }
#pragma unroll
        for (int o = 1; o < 4; o <<= 1) {
            ps0 += __shfl_xor_sync(0xffffffff, ps0, o);
            ps1 += __shfl_xor_sync(0xffffffff, ps1, o);
        }
        sum0 = sum0 * esc0 + ps0;
        sum1 = sum1 * esc1 + ps1;
#pragma unroll
        for (int nt = 0; nt < 8; nt++) {
            out[nt][0] *= esc0; out[nt][1] *= esc0;
            out[nt][2] *= esc1; out[nt][3] *= esc1;
        }

#pragma unroll
        for (int ks2 = 0; ks2 < 4; ks2++) {
            float* s0v = sc[2 * ks2];
            float* s1v = sc[2 * ks2 + 1];
            float h00 = __bfloat162float(__float2bfloat16(s0v[0]));
            float h01 = __bfloat162float(__float2bfloat16(s0v[1]));
            float h02 = __bfloat162float(__float2bfloat16(s0v[2]));
            float h03 = __bfloat162float(__float2bfloat16(s0v[3]));
            float h10 = __bfloat162float(__float2bfloat16(s1v[0]));
            float h11 = __bfloat162float(__float2bfloat16(s1v[1]));
            float h12 = __bfloat162float(__float2bfloat16(s1v[2]));
            float h13 = __bfloat162float(__float2bfloat16(s1v[3]));
            unsigned ph[4], pl[4];
            ph[0] = pack_bf16(s0v[0], s0v[1]);
            ph[1] = pack_bf16(s0v[2], s0v[3]);
            ph[2] = pack_bf16(s1v[0], s1v[1]);
            ph[3] = pack_bf16(s1v[2], s1v[3]);
            pl[0] = pack_bf16(s0v[0] - h00, s0v[1] - h01);
            pl[1] = pack_bf16(s0v[2] - h02, s0v[3] - h03);
            pl[2] = pack_bf16(s1v[0] - h10, s1v[1] - h11);
            pl[3] = pack_bf16(s1v[2] - h12, s1v[3] - h13);
            const unsigned kOfs = (unsigned)(ks2 * 16 * ATS * 4);
#pragma unroll
            for (int ntp = 0; ntp < 4; ntp++) {
                unsigned vb4[4], vbl4[4];
                LDSM4T(vb4,  VhS + vRelA[ntp] + kOfs);
                LDSM4T(vbl4, VlS + vRelA[ntp] + kOfs);
#pragma unroll
                for (int s = 0; s < 2; s++) {
                    int nt = 2 * ntp + s;
                    unsigned vbh[2] = {vb4[2 * s], vb4[2 * s + 1]};
                    unsigned vbl[2] = {vbl4[2 * s], vbl4[2 * s + 1]};
                    mma_bf16(out[nt], ph, vbh);
                    mma_bf16(out[nt], ph, vbl);
                    mma_bf16(out[nt], pl, vbh);
                }
            }
        }
    }

    if (j_start > 0) {
        float mn0 = fmaxf(m0, 0.f), mn1 = fmaxf(m1, 0.f);
        float esc0 = __expf(m0 - mn0), esc1 = __expf(m1 - mn1);
        float e0 = __expf(0.f - mn0), e1 = __expf(0.f - mn1);
        sum0 = sum0 * esc0 + 4.f * e0;
        sum1 = sum1 * esc1 + 4.f * e1;
#pragma unroll
        for (int nt = 0; nt < 8; nt++) {
            int col = nt * 8 + 2 * (lane & 3);
            out[nt][0] = out[nt][0] * esc0 + e0 * Vg4[col];
            out[nt][1] = out[nt][1] * esc0 + e0 * Vg4[col + 1];
            out[nt][2] = out[nt][2] * esc1 + e1 * Vg4[col];
            out[nt][3] = out[nt][3] * esc1 + e1 * Vg4[col + 1];
        }
    }

    float inv0 = 1.f / sum0, inv1 = 1.f / sum1;
    const int r0 = i0 + wq * 16 + (lane >> 2);

    // ---- fused global attention (q reconstructed = hi + lo) ----
    float w[2][4], deninv[2];
#pragma unroll
    for (int rr = 0; rr < 2; rr++) {
        int r = r0 + rr * 8;
        size_t qb = (size_t)r * DMODEL + h * HDIM;
        float dot[4] = {0.f, 0.f, 0.f, 0.f};
#pragma unroll
        for (int ks = 0; ks < 8; ks++) {
#pragma unroll
            for (int e2 = 0; e2 < 2; e2++) {
                int cc = ks * 8 + (lane & 3) + e2 * 4;
                float qv = __bfloat162float(g_Qbh[qb + cc]) +
                           __bfloat162float(g_Qbl[qb + cc]);
#pragma unroll
                for (int t = 0; t < 4; t++)
                    dot[t] = fmaf(qv, KG4[t * HDIM + cc], dot[t]);
            }
        }
#pragma unroll
        for (int t = 0; t < 4; t++) {
#pragma unroll
            for (int o = 1; o < 4; o <<= 1)
                dot[t] += __shfl_xor_sync(0xffffffff, dot[t], o);
            dot[t] *= 0.125f;
        }
        float mg = fmaxf(fmaxf(dot[0], dot[1]), fmaxf(dot[2], dot[3]));
        float den = 0.f;
#pragma unroll
        for (int t = 0; t < 4; t++) { w[rr][t] = __expf(dot[t] - mg); den += w[rr][t]; }
        deninv[rr] = 1.f / den;
    }

#pragma unroll
    for (int nt = 0; nt < 8; nt++) {
#pragma unroll
        for (int e = 0; e < 4; e++) {
            int rr = (e & 2) ? 1 : 0;
            int col = nt * 8 + 2 * (lane & 3) + (e & 1);
            float g = (w[rr][0] * VG4[0 * HDIM + col] + w[rr][1] * VG4[1 * HDIM + col] +
                       w[rr][2] * VG4[2 * HDIM + col] + w[rr][3] * VG4[3 * HDIM + col]) * deninv[rr];
            float v = out[nt][e] * (rr ? inv1 : inv0) + g;
            size_t idx = (size_t)(r0 + rr * 8) * DMODEL + h * HDIM + col;
            __nv_bfloat16 hb = __float2bfloat16(v);
            g_Bh[idx] = hb;
            g_Bl[idx] = __float2bfloat16(v - __bfloat162float(hb));
        }
    }
}

// ---------------------------------------------------------------------------
// launch
// ---------------------------------------------------------------------------
extern "C" void kernel_launch(void* const* d_in, const int* in_sizes, int n_in,
                              void* d_out, int out_size)
{
    const float* x     = (const float*)d_in[0];
    const float* cos_t = (const float*)d_in[1];
    const float* sin_t = (const float*)d_in[2];
    const int*   pos   = (const int*)d_in[3];
    P4 ws;
    ws.p[0] = (const float*)d_in[4];    // Wqs
    ws.p[1] = (const float*)d_in[5];    // Wks
    ws.p[2] = (const float*)d_in[6];    // Wvs
    ws.p[3] = (const float*)d_in[10];   // Wo
    const float* Wkg = (const float*)d_in[8];
    const float* Wvg = (const float*)d_in[9];
    float* out = (float*)d_out;

    static int attrs_set = 0;
    int attn_smem = ATT_SMEM_WORDS * 4;
    if (!attrs_set) {
        cudaFuncSetAttribute(attn_kernel,
                             cudaFuncAttributeMaxDynamicSharedMemorySize, attn_smem);
        cudaFuncSetAttribute(proj_kernel,
                             cudaFuncAttributeMaxDynamicSharedMemorySize, GEMM_SMEM_BYTES);
        cudaFuncSetAttribute(out_gemm_kernel,
                             cudaFuncAttributeMaxDynamicSharedMemorySize, GEMM_SMEM_BYTES);
        attrs_set = 1;
    }

    prep_kernel<<<PREP_BLOCKS, 256>>>(x, ws, Wkg, Wvg);
    kgvg_reduce_kernel<<<(2 * NGLOB * DMODEL) / 256, 256>>>();

    dim3 gp(DMODEL / 128, S_LEN / 128, 3);
    proj_kernel<<<gp, 256, GEMM_SMEM_BYTES>>>(cos_t, sin_t, pos);

    dim3 ga(NHEADS, S_LEN / 64);
    attn_kernel<<<ga, 128, attn_smem>>>();

    dim3 go(DMODEL / 128, S_LEN / 128);
    out_gemm_kernel<<<go, 256, GEMM_SMEM_BYTES>>>(out);
}